// round 1
// baseline (speedup 1.0000x reference)
#include <cuda_runtime.h>
#include <cuda_bf16.h>

// Output layout: [muTE (N floats)] ++ [M (N*N floats, row-major)]
// h = 0 (hunter), p = 1 (prey).
//
// M is zero except:
//   row 0:  +v[j]           row 1:  -v[j]
//   col 0:  +v[i]           col 1:  -v[i]
//   (0,0) = 2*n3_hhp + hp   (1,1) = -2*n3_pph + hp
//   (0,1) = (1,0) = -n3_hhp + n3_hpp - hp
// with v[j] = mu[j]*(var01 - 2*mu0*mu1) + mu1*var[0,j] + mu0*var[1,j],
// v[0] = v[1] = 0, and var[:,0] == var[0,:] by symmetry (bitwise, since
// var = 0.5*(a + a^T)).
//
// muTE is zero except muTE[0] = hp, muTE[1] = -hp, hp = var[0,1].

__global__ void eatrxn_fused_kernel(const float* __restrict__ mu,
                                    const float* __restrict__ var,
                                    float* __restrict__ out,
                                    unsigned int total4,
                                    unsigned int N,
                                    unsigned int shift,
                                    unsigned int mask) {
    unsigned int t = blockIdx.x * blockDim.x + threadIdx.x;
    if (t >= total4) return;
    unsigned int off = t << 2;  // element offset of this float4

    float4 r = make_float4(0.f, 0.f, 0.f, 0.f);

    if (off < N) {
        // muTE region
        if (off == 0u) {
            float hp = __ldg(&var[1]);
            r.x = hp;
            r.y = -hp;
        }
    } else {
        unsigned int m = off - N;       // element index within M
        unsigned int i = m >> shift;    // row
        unsigned int j = m & mask;      // col (float4 spans j..j+3, same row)

        if (i < 2u) {
            // Rows 0 (sign +) and 1 (sign -): value = s * v[j..j+3]
            float mu0 = __ldg(&mu[0]);
            float mu1 = __ldg(&mu[1]);
            float var01 = __ldg(&var[1]);
            float c = var01 - 2.f * mu0 * mu1;
            float s = (i == 0u) ? 1.f : -1.f;
            float vv[4];
            #pragma unroll
            for (int q = 0; q < 4; ++q) {
                unsigned int jj = j + (unsigned int)q;
                float vj;
                if (jj < 2u) {
                    vj = 0.f;   // loop excludes j == prey, j == hunter
                } else {
                    vj = fmaf(__ldg(&mu[jj]), c,
                          fmaf(mu1, __ldg(&var[jj]),         // var[0, jj]
                               mu0 * __ldg(&var[N + jj])));  // var[1, jj]
                }
                vv[q] = s * vj;
            }
            r.x = vv[0]; r.y = vv[1]; r.z = vv[2]; r.w = vv[3];

            if (j == 0u) {
                // Special 2x2 block
                float var00 = __ldg(&var[0]);
                float var11 = __ldg(&var[N + 1]);
                float hp = var01;
                // n3_pph = n3(p,p,h), n3_hhp = n3(h,h,p), n3_hpp = n3(h,p,p)
                float n3_pph = -2.f * mu1 * mu1 * mu0 + 2.f * mu1 * var01 + mu0 * var11;
                float n3_hhp = -2.f * mu0 * mu0 * mu1 + 2.f * mu0 * var01 + mu1 * var00;
                float n3_hpp = -2.f * mu0 * mu1 * mu1 + mu0 * var11 + 2.f * mu1 * var01;
                float chp = -n3_hhp + n3_hpp - hp;
                if (i == 0u) {
                    r.x = 2.f * n3_hhp + hp;   // (0,0)
                    r.y = chp;                 // (0,1)
                } else {
                    r.x = chp;                 // (1,0)
                    r.y = -2.f * n3_pph + hp;  // (1,1)
                }
            }
        } else if (j == 0u) {
            // Columns 0/1 of rows i >= 2: +v[i], -v[i]
            float mu0 = __ldg(&mu[0]);
            float mu1 = __ldg(&mu[1]);
            float var01 = __ldg(&var[1]);
            float c = var01 - 2.f * mu0 * mu1;
            float vi = fmaf(__ldg(&mu[i]), c,
                        fmaf(mu1, __ldg(&var[i]),            // var[0, i]
                             mu0 * __ldg(&var[N + i])));     // var[1, i]
            r.x = vi;
            r.y = -vi;
        }
        // everything else: zeros
    }

    reinterpret_cast<float4*>(out)[t] = r;
}

// Scalar tail (defensive; out_size for this problem is divisible by 4)
__global__ void eatrxn_tail_kernel(float* __restrict__ out,
                                   unsigned int start, unsigned int count) {
    unsigned int t = blockIdx.x * blockDim.x + threadIdx.x;
    if (t < count) out[start + t] = 0.f;  // tail lies deep inside zero region of M
}

extern "C" void kernel_launch(void* const* d_in, const int* in_sizes, int n_in,
                              void* d_out, int out_size) {
    const float* mu  = (const float*)d_in[0];
    const float* var = (const float*)d_in[1];
    float* out = (float*)d_out;

    unsigned int N = (unsigned int)in_sizes[0];   // 8192
    unsigned int shift = 0;
    while ((1u << shift) < N) ++shift;            // N is a power of two (8192 -> 13)
    unsigned int mask = N - 1u;

    unsigned int total4 = (unsigned int)(out_size / 4);
    unsigned int rem    = (unsigned int)(out_size - (long long)total4 * 4);

    const int TPB = 256;
    unsigned int blocks = (total4 + TPB - 1) / TPB;
    eatrxn_fused_kernel<<<blocks, TPB>>>(mu, var, out, total4, N, shift, mask);

    if (rem > 0) {
        eatrxn_tail_kernel<<<1, 32>>>(out, total4 * 4u, rem);
    }
}